// round 13
// baseline (speedup 1.0000x reference)
#include <cuda_runtime.h>
#include <cuda_fp16.h>
#include <cstdint>

#define BB 128
#define TT 512
#define HH 512
#define D2 1024
#define NOUT 64
#define VN 16
#define DACT 10

#define KZ 2.8853900817779268f    // 2*log2(e), for tanh via ex2
#define KF -1.4426950408889634f   // -log2(e), for sigmoid via ex2

// device scratch (no allocations allowed)
__device__ __half g_h[(size_t)BB * TT * D2];   // 134 MB relu(out) [b][t][d], fp16
__device__ float g_wp[(size_t)BB * 32 * TT];   // warp logit partials [b][row][t]

__device__ __forceinline__ float fex2(float x) {
    float y; asm("ex2.approx.f32 %0, %1;" : "=f"(y) : "f"(x)); return y;
}
__device__ __forceinline__ float frcp(float x) {
    float y; asm("rcp.approx.f32 %0, %1;" : "=f"(y) : "f"(x)); return y;
}
__device__ __forceinline__ __half2 bits2h2(unsigned v) {
    return *reinterpret_cast<__half2*>(&v);
}

// ---------------- K1: fused gate-GEMM + fo_pool scan, shared-rcp + SW pipeline ----------
// block = (b, unit); unit = dir*4 + q; 128 threads = h in [q*128, q*128+128)
// Math (validated round 9, rel_err 1e-5):
//   ez=ex2(KZ*az), ef=ex2(KF*af), eo=ex2(KF*ao)   [scales folded into weights+tables]
//   d1=ez+1; em=ef*ez-ef; den=(d1*(1+ef))*(eo+1); r=rcp(den); d3=eo+1
//   num = c*d1 + em;  h = num*r (= o*c_new);  c_new = h*d3;  hr = max(h,0)
// SW pipeline: state (d1,em,r,d3) for iter i+1 computed during iter i's body;
// the c-chain is only 3 fma-pipe ops, all MUFU off the critical path.
// smem (32256 B): tzf float2[VN*128] | ts2 float2[TT] | to float[VN*128] | vv short[TT] | buf float[4*160]
extern __shared__ float s_raw[];

__global__ void __launch_bounds__(128, 7) scan_kernel(
    const float* __restrict__ x,   // (B,T,3)
    const float* __restrict__ emb, // (16,10)
    const float* __restrict__ Wf, const float* __restrict__ bfw,
    const float* __restrict__ Wb, const float* __restrict__ bbw,
    const float* __restrict__ Mu)  // (2H,1)
{
    const int b    = blockIdx.x;
    const int unit = blockIdx.y;
    const int dir  = unit >> 2;
    const int q    = unit & 3;
    const int tid  = threadIdx.x;
    const int h    = q * 128 + tid;

    float2* tzf = (float2*)s_raw;                    // VN*128 float2 (16384 B)
    float2* ts2 = tzf + VN * 128;                    // TT float2     (4096 B)
    float*  to  = (float*)(ts2 + TT);                // VN*128        (8192 B)
    short*  vv  = (short*)(to + VN * 128);           // TT            (1024 B)
    float*  buf = (float*)(vv + TT);                 // 4*160         (2560 B)

    const float* W    = dir ? Wb : Wf;
    const float* bias = dir ? bbw : bfw;

    // stage x row into smem
    for (int t = tid; t < TT; t += 128) {
        const float* xp = x + ((size_t)b * TT + t) * 3;
        ts2[t] = make_float2(xp[0], xp[1]);
        vv[t]  = (short)(((int)xp[2]) << 7);         // pre-scaled v*128
    }

    const int ch_z = h, ch_f = HH + h, ch_o = 2 * HH + h;
    const float wz0 = KZ * W[ch_z], wz1 = KZ * W[1536 + ch_z];
    const float wf0 = KF * W[ch_f], wf1 = KF * W[1536 + ch_f];
    const float wo0 = KF * W[ch_o], wo1 = KF * W[1536 + ch_o];

    // build tables (bias folded, then gate-scaled)
    {
        float wk[DACT];
#pragma unroll
        for (int k = 0; k < DACT; k++) wk[k] = W[(2 + k) * 1536 + ch_z];
        const float bz = bias[ch_z];
        for (int v = 0; v < VN; v++) {
            float a = bz;
#pragma unroll
            for (int k = 0; k < DACT; k++) a = fmaf(emb[v * DACT + k], wk[k], a);
            ((float*)tzf)[(v * 128 + tid) * 2] = KZ * a;
        }
#pragma unroll
        for (int k = 0; k < DACT; k++) wk[k] = W[(2 + k) * 1536 + ch_f];
        const float bfv = bias[ch_f];
        for (int v = 0; v < VN; v++) {
            float a = bfv;
#pragma unroll
            for (int k = 0; k < DACT; k++) a = fmaf(emb[v * DACT + k], wk[k], a);
            ((float*)tzf)[(v * 128 + tid) * 2 + 1] = KF * a;
        }
#pragma unroll
        for (int k = 0; k < DACT; k++) wk[k] = W[(2 + k) * 1536 + ch_o];
        const float bo = bias[ch_o];
        for (int v = 0; v < VN; v++) {
            float a = bo;
#pragma unroll
            for (int k = 0; k < DACT; k++) a = fmaf(emb[v * DACT + k], wk[k], a);
            to[v * 128 + tid] = KF * a;
        }
    }
    const int d = dir * HH + h;
    const float mu = Mu[d];
    __syncthreads();

    const int lane = tid & 31;
    const int wid  = tid >> 5;
    float* bufw = buf + wid * 160;                   // 32 x 5 padded tile
    const int rstep = dir ? -D2 : D2;

    float c = 0.0f;
    __half* hp = g_h + ((size_t)b * TT + (dir ? TT - 1 : 0)) * D2 + d;
    float* wp_out = g_wp + ((size_t)b * 32 + unit * 4 + wid) * TT;

    // pipeline state (ping-pong): d1, em, r, d3
    float s_d1[2], s_em[2], s_r[2], s_d3[2];

#define COMPUTE_STATE(I, SLOT)                                            \
    {                                                                     \
        const int ii = (I);                                               \
        const int t  = dir ? (TT - 1 - ii) : ii;                          \
        const float2 tt = ts2[t];                                         \
        const int off = ((int)vv[t]) + tid;                               \
        const float2 zf = tzf[off];                                       \
        const float ob = to[off];                                         \
        const float az = fmaf(tt.x, wz0, fmaf(tt.y, wz1, zf.x));          \
        const float af = fmaf(tt.x, wf0, fmaf(tt.y, wf1, zf.y));          \
        const float ao = fmaf(tt.x, wo0, fmaf(tt.y, wo1, ob));            \
        const float ez = fex2(az);                                        \
        const float ef = fex2(af);                                        \
        const float eo = fex2(ao);                                        \
        const float D1 = ez + 1.0f;                                       \
        const float D3 = eo + 1.0f;                                       \
        const float den12 = fmaf(D1, ef, D1);                             \
        s_d1[SLOT] = D1;                                                  \
        s_em[SLOT] = fmaf(ef, ez, -ef);                                   \
        s_d3[SLOT] = D3;                                                  \
        s_r[SLOT]  = frcp(den12 * D3);                                    \
    }

    COMPUTE_STATE(0, 0);

    for (int ch = 0; ch < TT / 4; ch++) {
#pragma unroll
        for (int j = 0; j < 4; j++) {
            const int i = ch * 4 + j;
            const int cs = i & 1;
            const int ip = (i + 1 < TT) ? (i + 1) : i;   // clamp (last recompute unused)
            // issue next iteration's independent work first (LDS/FFMA/MUFU)
            COMPUTE_STATE(ip, cs ^ 1);
            // c-update for current iteration from last round's registers
            const float num  = fmaf(c, s_d1[cs], s_em[cs]);
            const float hpre = num * s_r[cs];                // o * c_new
            c = hpre * s_d3[cs];                             // c_new
            const float hr = fmaxf(hpre, 0.0f);
            *hp = __float2half_rn(hr); hp += rstep;
            bufw[lane * 5 + j] = hr * mu;
        }
        __syncwarp();
        {
            const int tl = lane >> 3;                // t_local 0..3
            const int s  = lane & 7;
            float p = bufw[(s     ) * 5 + tl]
                    + bufw[(s +  8) * 5 + tl]
                    + bufw[(s + 16) * 5 + tl]
                    + bufw[(s + 24) * 5 + tl];
            p += __shfl_xor_sync(0xffffffffu, p, 4);
            p += __shfl_xor_sync(0xffffffffu, p, 2);
            p += __shfl_xor_sync(0xffffffffu, p, 1);
            if (s == 0) {
                const int i = ch * 4 + tl;
                wp_out[dir ? (TT - 1 - i) : i] = p;
            }
        }
        __syncwarp();
    }
#undef COMPUTE_STATE
}

// ---------------- K2: fused softmax + context + GEMV, one block per batch ----------------
__global__ void __launch_bounds__(1024) finalize_kernel(
    const float* __restrict__ W_out,  // (64, 1024)
    const float* __restrict__ b_out,  // (64,)
    float* __restrict__ out)          // (B, 64)
{
    __shared__ float sm_acc[8 * 1024];   // phase2 partials; phase1 reuses first 1024
    __shared__ float sm_attn[TT];
    __shared__ float sm_ctx[D2];
    __shared__ float red[32];

    const int b   = blockIdx.x;
    const int tid = threadIdx.x;
    const int lane = tid & 31, wid = tid >> 5;

    // ---- phase 1a: reduce 32 warp-partial rows -> logits ----
    {
        const int t  = tid & 511;
        const int hf = tid >> 9;                      // 0/1: rows [0,16) or [16,32)
        const float* wp = g_wp + ((size_t)b * 32 + hf * 16) * TT + t;
        float s = 0.0f;
#pragma unroll
        for (int r = 0; r < 16; r++) s += wp[(size_t)r * TT];
        sm_acc[hf * 512 + t] = s;
    }
    __syncthreads();
    float s_logit = -1e30f;
    if (tid < TT) s_logit = sm_acc[tid] + sm_acc[512 + tid];

    // ---- phase 1b: softmax over 512 ----
    float m = s_logit;
#pragma unroll
    for (int o = 16; o; o >>= 1) m = fmaxf(m, __shfl_xor_sync(0xffffffffu, m, o));
    if (lane == 0) red[wid] = m;
    __syncthreads();
    if (wid == 0) {
        float v = red[lane];
#pragma unroll
        for (int o = 16; o; o >>= 1) v = fmaxf(v, __shfl_xor_sync(0xffffffffu, v, o));
        if (lane == 0) red[0] = v;
    }
    __syncthreads();
    m = red[0];
    __syncthreads();

    float e = (tid < TT) ? fex2(1.4426950408889634f * (s_logit - m)) : 0.0f;
    float su = e;
#pragma unroll
    for (int o = 16; o; o >>= 1) su += __shfl_xor_sync(0xffffffffu, su, o);
    if (lane == 0) red[wid] = su;
    __syncthreads();
    if (wid == 0) {
        float v = red[lane];
#pragma unroll
        for (int o = 16; o; o >>= 1) v += __shfl_xor_sync(0xffffffffu, v, o);
        if (lane == 0) red[0] = v;
    }
    __syncthreads();
    if (tid < TT) sm_attn[tid] = e / red[0];
    __syncthreads();

    // ---- phase 2: context. 8 t-groups x 128 d-chunks; double-buffered SW pipeline ----
    {
        const int tg = tid >> 7;                      // t-group 0..7
        const int dc = (tid & 127) * 8;               // d base
        const __half* hb = g_h + (size_t)b * TT * D2 + dc;
        float acc[8];
#pragma unroll
        for (int j = 0; j < 8; j++) acc[j] = 0.0f;

        uint4 cur[4], nxt[4];
        float ac[4], an[4];
#pragma unroll
        for (int i = 0; i < 4; i++) {
            const int t = tg + i * 8;
            cur[i] = *(const uint4*)(hb + (size_t)t * D2);
            ac[i] = sm_attn[t];
        }
#pragma unroll 2
        for (int g = 0; g < 16; g++) {
            const int gn = (g + 1) & 15;             // wraps to 0 on last (harmless reload)
#pragma unroll
            for (int i = 0; i < 4; i++) {
                const int t = tg + (gn * 4 + i) * 8;
                nxt[i] = *(const uint4*)(hb + (size_t)t * D2);
                an[i] = sm_attn[t];
            }
#pragma unroll
            for (int i = 0; i < 4; i++) {
                const float a = ac[i];
                float2 q0 = __half22float2(bits2h2(cur[i].x));
                float2 q1 = __half22float2(bits2h2(cur[i].y));
                float2 q2 = __half22float2(bits2h2(cur[i].z));
                float2 q3 = __half22float2(bits2h2(cur[i].w));
                acc[0] = fmaf(a, q0.x, acc[0]); acc[1] = fmaf(a, q0.y, acc[1]);
                acc[2] = fmaf(a, q1.x, acc[2]); acc[3] = fmaf(a, q1.y, acc[3]);
                acc[4] = fmaf(a, q2.x, acc[4]); acc[5] = fmaf(a, q2.y, acc[5]);
                acc[6] = fmaf(a, q3.x, acc[6]); acc[7] = fmaf(a, q3.y, acc[7]);
            }
#pragma unroll
            for (int i = 0; i < 4; i++) { cur[i] = nxt[i]; ac[i] = an[i]; }
        }
#pragma unroll
        for (int j = 0; j < 8; j++) sm_acc[tg * 1024 + dc + j] = acc[j];
    }
    __syncthreads();

    // reduce 8 t-group partials per d, relu -> ctx
    {
        float v0 = sm_acc[0 * 1024 + tid] + sm_acc[1 * 1024 + tid];
        float v1 = sm_acc[2 * 1024 + tid] + sm_acc[3 * 1024 + tid];
        float v2 = sm_acc[4 * 1024 + tid] + sm_acc[5 * 1024 + tid];
        float v3 = sm_acc[6 * 1024 + tid] + sm_acc[7 * 1024 + tid];
        sm_ctx[tid] = fmaxf((v0 + v1) + (v2 + v3), 0.0f);
    }
    __syncthreads();

    // ---- phase 3: GEMV 64 x 1024 (32 warps x 2 rows) ----
#pragma unroll
    for (int r = 0; r < 2; r++) {
        const int o = wid * 2 + r;
        const float* wrow = W_out + (size_t)o * D2;
        float v = 0.0f;
#pragma unroll
        for (int k = 0; k < D2 / 32; k++)
            v = fmaf(sm_ctx[lane + k * 32], wrow[lane + k * 32], v);
#pragma unroll
        for (int off = 16; off; off >>= 1) v += __shfl_xor_sync(0xffffffffu, v, off);
        if (lane == 0) out[(size_t)b * NOUT + o] = v + b_out[o];
    }
}

extern "C" void kernel_launch(void* const* d_in, const int* in_sizes, int n_in,
                              void* d_out, int out_size) {
    const float* x     = (const float*)d_in[0];
    const float* emb   = (const float*)d_in[1];
    const float* Wf    = (const float*)d_in[2];
    const float* bf    = (const float*)d_in[3];
    const float* Wb    = (const float*)d_in[4];
    const float* bb    = (const float*)d_in[5];
    const float* Mu    = (const float*)d_in[6];
    const float* W_out = (const float*)d_in[7];
    const float* b_out = (const float*)d_in[8];
    float* out = (float*)d_out;

    // scan smem: 16384 + 4096 + 8192 + 1024 + 2560 = 32256 B (< 48KB default)
    scan_kernel<<<dim3(BB, 8), 128, 32256>>>(x, emb, Wf, bf, Wb, bb, Mu);
    finalize_kernel<<<BB, 1024>>>(W_out, b_out, out);
}

// round 15
// speedup vs baseline: 1.5449x; 1.5449x over previous
#include <cuda_runtime.h>
#include <cuda_fp16.h>
#include <cstdint>

#define BB 128
#define TT 512
#define HH 512
#define D2 1024
#define NOUT 64
#define VN 16
#define DACT 10

// device scratch (no allocations allowed)
__device__ __half g_h[(size_t)BB * TT * D2];   // 134 MB relu(out) [b][t][d], fp16
__device__ float g_wp[(size_t)BB * 16 * TT];   // warp logit partials [b][row][t]

__device__ __forceinline__ float fex2(float x) {
    float y; asm("ex2.approx.f32 %0, %1;" : "=f"(y) : "f"(x)); return y;
}
__device__ __forceinline__ __half2 qtanh_h2(__half2 x) {
    unsigned xi = *reinterpret_cast<unsigned*>(&x);
    unsigned yi;
    asm("tanh.approx.f16x2 %0, %1;" : "=r"(yi) : "r"(xi));
    return *reinterpret_cast<__half2*>(&yi);
}
__device__ __forceinline__ unsigned h2bits(__half2 v) {
    return *reinterpret_cast<unsigned*>(&v);
}
__device__ __forceinline__ __half2 bits2h2(unsigned v) {
    return *reinterpret_cast<__half2*>(&v);
}
// 256-bit evict-first load (sm_103a requires .v4.b64 width for the L2 hint):
// fetched lines become preferred eviction victims so scan-written g_h lines
// stay resident in L2 while finalize streams.
__device__ __forceinline__ ulonglong4 ldg_ef_u8(const void* p) {
    ulonglong4 v;
    asm volatile("ld.global.L2::evict_first.v4.b64 {%0,%1,%2,%3}, [%4];"
                 : "=l"(v.x), "=l"(v.y), "=l"(v.z), "=l"(v.w) : "l"(p));
    return v;
}

// ---------------- K1: half2-paired gate-GEMM + fo_pool scan (round-10/12 proven) ----------
// grid (B, 8); unit = dir*4 + q; 64 threads; thread owns channel pair
// d0 = q*128 + tid*2 within its direction.
// smem (18688 B): tblzf uint2[VN*64] | tblo half2[VN*64] | tsa half2[TT] | tsb half2[TT]
//                 | vv short[TT] | buf float[2*160]
extern __shared__ float s_raw[];

__global__ void __launch_bounds__(64, 7) scan_kernel(
    const float* __restrict__ x,   // (B,T,3)
    const float* __restrict__ emb, // (16,10)
    const float* __restrict__ Wf, const float* __restrict__ bfw,
    const float* __restrict__ Wb, const float* __restrict__ bbw,
    const float* __restrict__ Mu)  // (2H,1)
{
    const int b    = blockIdx.x;
    const int unit = blockIdx.y;          // 0..7
    const int dir  = unit >> 2;
    const int q    = unit & 3;
    const int tid  = threadIdx.x;         // 0..63
    const int d0   = q * 128 + tid * 2;   // channel pair within dir

    uint2*   tblzf = (uint2*)s_raw;                    // VN*64 uint2  (8192 B)
    __half2* tblo  = (__half2*)(tblzf + VN * 64);      // VN*64 half2  (4096 B)
    __half2* tsa   = tblo + VN * 64;                   // TT half2     (2048 B)
    __half2* tsb   = tsa + TT;                         // TT half2     (2048 B)
    short*   vv    = (short*)(tsb + TT);               // TT           (1024 B)
    float*   buf   = (float*)(vv + TT);                // 2*160        (1280 B)

    const float* W    = dir ? Wb : Wf;
    const float* bias = dir ? bbw : bfw;

    // stage x row into smem (splatted half2)
    for (int t = tid; t < TT; t += 64) {
        const float* xp = x + ((size_t)b * TT + t) * 3;
        tsa[t] = __half2half2(__float2half_rn(xp[0]));
        tsb[t] = __half2half2(__float2half_rn(xp[1]));
        vv[t]  = (short)(((int)xp[2]) << 6);           // v*64
    }

    const int ca = d0, cb = d0 + 1;
    // ts-part weights per gate, channel pair. f/o gates prescaled by 0.5 (sigmoid trick).
    const __half2 wz0 = __floats2half2_rn(W[ca], W[cb]);
    const __half2 wz1 = __floats2half2_rn(W[1536 + ca], W[1536 + cb]);
    const __half2 wf0 = __floats2half2_rn(0.5f * W[HH + ca], 0.5f * W[HH + cb]);
    const __half2 wf1 = __floats2half2_rn(0.5f * W[1536 + HH + ca], 0.5f * W[1536 + HH + cb]);
    const __half2 wo0 = __floats2half2_rn(0.5f * W[2 * HH + ca], 0.5f * W[2 * HH + cb]);
    const __half2 wo1 = __floats2half2_rn(0.5f * W[1536 + 2 * HH + ca], 0.5f * W[1536 + 2 * HH + cb]);

    // build tables (f32 accumulate, store half2). z: full; f,o: prescaled 0.5.
    {
        float wka[DACT], wkb[DACT];
#pragma unroll
        for (int k = 0; k < DACT; k++) {
            wka[k] = W[(2 + k) * 1536 + ca];
            wkb[k] = W[(2 + k) * 1536 + cb];
        }
        const float bza = bias[ca], bzb = bias[cb];
        for (int v = 0; v < VN; v++) {
            float aa = bza, ab = bzb;
#pragma unroll
            for (int k = 0; k < DACT; k++) {
                const float e = emb[v * DACT + k];
                aa = fmaf(e, wka[k], aa);
                ab = fmaf(e, wkb[k], ab);
            }
            tblzf[v * 64 + tid].x = h2bits(__floats2half2_rn(aa, ab));
        }
#pragma unroll
        for (int k = 0; k < DACT; k++) {
            wka[k] = W[(2 + k) * 1536 + HH + ca];
            wkb[k] = W[(2 + k) * 1536 + HH + cb];
        }
        const float bfa = bias[HH + ca], bfb = bias[HH + cb];
        for (int v = 0; v < VN; v++) {
            float aa = bfa, ab = bfb;
#pragma unroll
            for (int k = 0; k < DACT; k++) {
                const float e = emb[v * DACT + k];
                aa = fmaf(e, wka[k], aa);
                ab = fmaf(e, wkb[k], ab);
            }
            tblzf[v * 64 + tid].y = h2bits(__floats2half2_rn(0.5f * aa, 0.5f * ab));
        }
#pragma unroll
        for (int k = 0; k < DACT; k++) {
            wka[k] = W[(2 + k) * 1536 + 2 * HH + ca];
            wkb[k] = W[(2 + k) * 1536 + 2 * HH + cb];
        }
        const float boa = bias[2 * HH + ca], bob = bias[2 * HH + cb];
        for (int v = 0; v < VN; v++) {
            float aa = boa, ab = bob;
#pragma unroll
            for (int k = 0; k < DACT; k++) {
                const float e = emb[v * DACT + k];
                aa = fmaf(e, wka[k], aa);
                ab = fmaf(e, wkb[k], ab);
            }
            tblo[v * 64 + tid] = __floats2half2_rn(0.5f * aa, 0.5f * ab);
        }
    }
    const float mua = Mu[dir * HH + ca];
    const float mub = Mu[dir * HH + cb];
    __syncthreads();

    const int lane = tid & 31;
    const int wid  = tid >> 5;            // 0..1
    float* bufw = buf + wid * 160;        // 32 x 5 padded tile
    const int rstep = dir ? -(D2 / 2) : (D2 / 2);   // in half2 units

    const __half2 hhalf = __half2half2(__float2half_rn(0.5f));
    const __half2 hzero = __half2half2(__float2half_rn(0.0f));
    __half2 c2 = hzero;

    __half2* hp = (__half2*)(g_h + ((size_t)b * TT + (dir ? TT - 1 : 0)) * D2
                             + (size_t)dir * HH + d0);
    float* wp_out = g_wp + ((size_t)b * 16 + unit * 2 + wid) * TT;

    for (int ch = 0; ch < TT / 4; ch++) {
#pragma unroll
        for (int j = 0; j < 4; j++) {
            const int i = ch * 4 + j;
            const int t = dir ? (TT - 1 - i) : i;
            const __half2 t0 = tsa[t];
            const __half2 t1 = tsb[t];
            const int off = ((int)vv[t]) + tid;
            const uint2 zfb = tblzf[off];
            const __half2 az = __hfma2(t0, wz0, __hfma2(t1, wz1, bits2h2(zfb.x)));
            const __half2 af = __hfma2(t0, wf0, __hfma2(t1, wf1, bits2h2(zfb.y)));
            const __half2 ao = __hfma2(t0, wo0, __hfma2(t1, wo1, tblo[off]));
            const __half2 z = qtanh_h2(az);
            const __half2 f = __hfma2(qtanh_h2(af), hhalf, hhalf);
            const __half2 o = __hfma2(qtanh_h2(ao), hhalf, hhalf);
            c2 = __hfma2(f, __hsub2(c2, z), z);      // f*c + (1-f)*z
            const __half2 hr = __hmax2(__hmul2(o, c2), hzero);
            *hp = hr; hp += rstep;
            const float2 hf2 = __half22float2(hr);
            bufw[lane * 5 + j] = fmaf(mua, hf2.x, mub * hf2.y);
        }
        __syncwarp();
        {
            const int tl = lane >> 3;                // t_local 0..3
            const int s  = lane & 7;
            float p = bufw[(s     ) * 5 + tl]
                    + bufw[(s +  8) * 5 + tl]
                    + bufw[(s + 16) * 5 + tl]
                    + bufw[(s + 24) * 5 + tl];
            p += __shfl_xor_sync(0xffffffffu, p, 4);
            p += __shfl_xor_sync(0xffffffffu, p, 2);
            p += __shfl_xor_sync(0xffffffffu, p, 1);
            if (s == 0) {
                const int i = ch * 4 + tl;
                wp_out[dir ? (TT - 1 - i) : i] = p;
            }
        }
        __syncwarp();
    }
}

// ---------------- K2: fused softmax + context + GEMV, one block per batch ----------------
// Phase 2: 16 t-groups x 64 d-chunks of 16; 32B evict_first loads, double-buffered.
// Padded partial tile: [8 rows][64 chunks * 17] (odd stride -> conflict-free).
#define ROWSTRIDE (64 * 17)   // 1088 floats per partial row

__global__ void __launch_bounds__(1024) finalize_kernel(
    const float* __restrict__ W_out,  // (64, 1024)
    const float* __restrict__ b_out,  // (64,)
    float* __restrict__ out)          // (B, 64)
{
    __shared__ float sm_acc[8 * ROWSTRIDE];  // 34816 B; phase1 reuses first 1024
    __shared__ float sm_attn[TT];
    __shared__ float sm_ctx[D2];
    __shared__ float red[32];

    const int b   = blockIdx.x;
    const int tid = threadIdx.x;
    const int lane = tid & 31, wid = tid >> 5;

    // ---- phase 1a: reduce 16 warp-partial rows -> logits ----
    {
        const int t  = tid & 511;
        const int hf = tid >> 9;                      // 0/1: rows [0,8) or [8,16)
        const float* wp = g_wp + ((size_t)b * 16 + hf * 8) * TT + t;
        float s = 0.0f;
#pragma unroll
        for (int r = 0; r < 8; r++) s += wp[(size_t)r * TT];
        sm_acc[hf * 512 + t] = s;
    }
    __syncthreads();
    float s_logit = -1e30f;
    if (tid < TT) s_logit = sm_acc[tid] + sm_acc[512 + tid];

    // ---- phase 1b: softmax over 512 ----
    float m = s_logit;
#pragma unroll
    for (int o = 16; o; o >>= 1) m = fmaxf(m, __shfl_xor_sync(0xffffffffu, m, o));
    if (lane == 0) red[wid] = m;
    __syncthreads();
    if (wid == 0) {
        float v = red[lane];
#pragma unroll
        for (int o = 16; o; o >>= 1) v = fmaxf(v, __shfl_xor_sync(0xffffffffu, v, o));
        if (lane == 0) red[0] = v;
    }
    __syncthreads();
    m = red[0];
    __syncthreads();

    float e = (tid < TT) ? fex2(1.4426950408889634f * (s_logit - m)) : 0.0f;
    float su = e;
#pragma unroll
    for (int o = 16; o; o >>= 1) su += __shfl_xor_sync(0xffffffffu, su, o);
    if (lane == 0) red[wid] = su;
    __syncthreads();
    if (wid == 0) {
        float v = red[lane];
#pragma unroll
        for (int o = 16; o; o >>= 1) v += __shfl_xor_sync(0xffffffffu, v, o);
        if (lane == 0) red[0] = v;
    }
    __syncthreads();
    if (tid < TT) sm_attn[tid] = e / red[0];
    __syncthreads();

    // ---- phase 2: context with 32B evict_first loads ----
    {
        const int tg  = tid >> 6;                     // t-group 0..15
        const int dcw = tid & 63;                     // d-chunk index (16 d each)
        const __half* hb = g_h + (size_t)b * TT * D2 + dcw * 16;

        float acc[16];
#pragma unroll
        for (int j = 0; j < 16; j++) acc[j] = 0.0f;

        ulonglong4 cur[2], nxt[2];
        float ac[2], an[2];
#pragma unroll
        for (int i = 0; i < 2; i++) {
            const int t = tg + i * 16;
            cur[i] = ldg_ef_u8(hb + (size_t)t * D2);
            ac[i] = sm_attn[t];
        }
        for (int g = 0; g < 16; g++) {
            const int gn = (g + 1) & 15;             // wraps on last (harmless reload)
#pragma unroll
            for (int i = 0; i < 2; i++) {
                const int t = tg + (gn * 2 + i) * 16;
                nxt[i] = ldg_ef_u8(hb + (size_t)t * D2);
                an[i] = sm_attn[t];
            }
#pragma unroll
            for (int i = 0; i < 2; i++) {
                const float a = ac[i];
#define ACC_U64(W64, BASE)                                             \
                {                                                      \
                    float2 qa = __half22float2(bits2h2((unsigned)(W64)));          \
                    float2 qb = __half22float2(bits2h2((unsigned)((W64) >> 32)));  \
                    acc[(BASE) + 0] = fmaf(a, qa.x, acc[(BASE) + 0]);  \
                    acc[(BASE) + 1] = fmaf(a, qa.y, acc[(BASE) + 1]);  \
                    acc[(BASE) + 2] = fmaf(a, qb.x, acc[(BASE) + 2]);  \
                    acc[(BASE) + 3] = fmaf(a, qb.y, acc[(BASE) + 3]);  \
                }
                ACC_U64(cur[i].x, 0);
                ACC_U64(cur[i].y, 4);
                ACC_U64(cur[i].z, 8);
                ACC_U64(cur[i].w, 12);
#undef ACC_U64
            }
#pragma unroll
            for (int i = 0; i < 2; i++) { cur[i] = nxt[i]; ac[i] = an[i]; }
        }

        // two-stage 16 -> 8 partial rows in padded smem
        float* sp = sm_acc + (tg & 7) * ROWSTRIDE + dcw * 17;
        if (tg < 8) {
#pragma unroll
            for (int j = 0; j < 16; j++) sp[j] = acc[j];
        }
        __syncthreads();
        if (tg >= 8) {
#pragma unroll
            for (int j = 0; j < 16; j++) sp[j] += acc[j];
        }
    }
    __syncthreads();

    // reduce 8 partial rows per d, relu -> ctx
    {
        const int chunk = tid >> 4, jj = tid & 15;
        const float* base = sm_acc + chunk * 17 + jj;
        float v0 = base[0 * ROWSTRIDE] + base[1 * ROWSTRIDE];
        float v1 = base[2 * ROWSTRIDE] + base[3 * ROWSTRIDE];
        float v2 = base[4 * ROWSTRIDE] + base[5 * ROWSTRIDE];
        float v3 = base[6 * ROWSTRIDE] + base[7 * ROWSTRIDE];
        sm_ctx[tid] = fmaxf((v0 + v1) + (v2 + v3), 0.0f);
    }
    __syncthreads();

    // ---- phase 3: GEMV 64 x 1024 (32 warps x 2 rows) ----
#pragma unroll
    for (int r = 0; r < 2; r++) {
        const int o = wid * 2 + r;
        const float* wrow = W_out + (size_t)o * D2;
        float v = 0.0f;
#pragma unroll
        for (int k = 0; k < D2 / 32; k++)
            v = fmaf(sm_ctx[lane + k * 32], wrow[lane + k * 32], v);
#pragma unroll
        for (int off = 16; off; off >>= 1) v += __shfl_xor_sync(0xffffffffu, v, off);
        if (lane == 0) out[(size_t)b * NOUT + o] = v + b_out[o];
    }
}

extern "C" void kernel_launch(void* const* d_in, const int* in_sizes, int n_in,
                              void* d_out, int out_size) {
    const float* x     = (const float*)d_in[0];
    const float* emb   = (const float*)d_in[1];
    const float* Wf    = (const float*)d_in[2];
    const float* bf    = (const float*)d_in[3];
    const float* Wb    = (const float*)d_in[4];
    const float* bb    = (const float*)d_in[5];
    const float* Mu    = (const float*)d_in[6];
    const float* W_out = (const float*)d_in[7];
    const float* b_out = (const float*)d_in[8];
    float* out = (float*)d_out;

    // scan smem: 8192 + 4096 + 2048 + 2048 + 1024 + 1280 = 18688 B (< 48KB default)
    scan_kernel<<<dim3(BB, 8), 64, 18688>>>(x, emb, Wf, bf, Wb, bb, Mu);
    finalize_kernel<<<BB, 1024>>>(W_out, b_out, out);
}

// round 16
// speedup vs baseline: 1.5453x; 1.0003x over previous
#include <cuda_runtime.h>
#include <cuda_fp16.h>
#include <cstdint>

#define BB 128
#define TT 512
#define HH 512
#define D2 1024
#define NOUT 64
#define VN 16
#define DACT 10

// device scratch (no allocations allowed)
__device__ __half g_h[(size_t)BB * TT * D2];   // 134 MB relu(out) [b][t][d], fp16
__device__ float g_wp[(size_t)BB * 16 * TT];   // warp logit partials [b][row][t]

__device__ __forceinline__ float fex2(float x) {
    float y; asm("ex2.approx.f32 %0, %1;" : "=f"(y) : "f"(x)); return y;
}
__device__ __forceinline__ __half2 qtanh_h2(__half2 x) {
    unsigned xi = *reinterpret_cast<unsigned*>(&x);
    unsigned yi;
    asm("tanh.approx.f16x2 %0, %1;" : "=r"(yi) : "r"(xi));
    return *reinterpret_cast<__half2*>(&yi);
}
__device__ __forceinline__ unsigned h2bits(__half2 v) {
    return *reinterpret_cast<unsigned*>(&v);
}
__device__ __forceinline__ __half2 bits2h2(unsigned v) {
    return *reinterpret_cast<__half2*>(&v);
}
// 256-bit evict-first load (sm_103a requires .v4.b64 width for the L2 hint)
__device__ __forceinline__ ulonglong4 ldg_ef_u8(const void* p) {
    ulonglong4 v;
    asm volatile("ld.global.L2::evict_first.v4.b64 {%0,%1,%2,%3}, [%4];"
                 : "=l"(v.x), "=l"(v.y), "=l"(v.z), "=l"(v.w) : "l"(p));
    return v;
}

// ---------------- K1: half2-paired gate-GEMM + fo_pool scan ----------------
// o-gate sigmoid via fp16 polynomial on the HFMA2 pipe (MUFU 3->2 h2tanh/iter):
//   o = 0.5 + 0.5 * P7(clamp(0.5*ao, +-1.5)),  P7(x) = x*(c1 + c3 s + c5 s^2 + c7 s^3)
// grid (B, 8); unit = dir*4 + q; 64 threads; thread owns channel pair d0 = q*128+tid*2.
// smem (18688 B): tblzf uint2[VN*64] | tblo half2[VN*64] | tsa half2[TT] | tsb half2[TT]
//                 | vv short[TT] | buf float[2*160]
extern __shared__ float s_raw[];

__global__ void __launch_bounds__(64, 7) scan_kernel(
    const float* __restrict__ x,   // (B,T,3)
    const float* __restrict__ emb, // (16,10)
    const float* __restrict__ Wf, const float* __restrict__ bfw,
    const float* __restrict__ Wb, const float* __restrict__ bbw,
    const float* __restrict__ Mu)  // (2H,1)
{
    const int b    = blockIdx.x;
    const int unit = blockIdx.y;          // 0..7
    const int dir  = unit >> 2;
    const int q    = unit & 3;
    const int tid  = threadIdx.x;         // 0..63
    const int d0   = q * 128 + tid * 2;   // channel pair within dir

    uint2*   tblzf = (uint2*)s_raw;                    // VN*64 uint2  (8192 B)
    __half2* tblo  = (__half2*)(tblzf + VN * 64);      // VN*64 half2  (4096 B)
    __half2* tsa   = tblo + VN * 64;                   // TT half2     (2048 B)
    __half2* tsb   = tsa + TT;                         // TT half2     (2048 B)
    short*   vv    = (short*)(tsb + TT);               // TT           (1024 B)
    float*   buf   = (float*)(vv + TT);                // 2*160        (1280 B)

    const float* W    = dir ? Wb : Wf;
    const float* bias = dir ? bbw : bfw;

    // stage x row into smem (splatted half2)
    for (int t = tid; t < TT; t += 64) {
        const float* xp = x + ((size_t)b * TT + t) * 3;
        tsa[t] = __half2half2(__float2half_rn(xp[0]));
        tsb[t] = __half2half2(__float2half_rn(xp[1]));
        vv[t]  = (short)(((int)xp[2]) << 6);           // v*64
    }

    const int ca = d0, cb = d0 + 1;
    // ts-part weights per gate, channel pair. f/o gates prescaled by 0.5 (sigmoid trick).
    const __half2 wz0 = __floats2half2_rn(W[ca], W[cb]);
    const __half2 wz1 = __floats2half2_rn(W[1536 + ca], W[1536 + cb]);
    const __half2 wf0 = __floats2half2_rn(0.5f * W[HH + ca], 0.5f * W[HH + cb]);
    const __half2 wf1 = __floats2half2_rn(0.5f * W[1536 + HH + ca], 0.5f * W[1536 + HH + cb]);
    const __half2 wo0 = __floats2half2_rn(0.5f * W[2 * HH + ca], 0.5f * W[2 * HH + cb]);
    const __half2 wo1 = __floats2half2_rn(0.5f * W[1536 + 2 * HH + ca], 0.5f * W[1536 + 2 * HH + cb]);

    // build tables (f32 accumulate, store half2). z: full; f,o: prescaled 0.5.
    {
        float wka[DACT], wkb[DACT];
#pragma unroll
        for (int k = 0; k < DACT; k++) {
            wka[k] = W[(2 + k) * 1536 + ca];
            wkb[k] = W[(2 + k) * 1536 + cb];
        }
        const float bza = bias[ca], bzb = bias[cb];
        for (int v = 0; v < VN; v++) {
            float aa = bza, ab = bzb;
#pragma unroll
            for (int k = 0; k < DACT; k++) {
                const float e = emb[v * DACT + k];
                aa = fmaf(e, wka[k], aa);
                ab = fmaf(e, wkb[k], ab);
            }
            tblzf[v * 64 + tid].x = h2bits(__floats2half2_rn(aa, ab));
        }
#pragma unroll
        for (int k = 0; k < DACT; k++) {
            wka[k] = W[(2 + k) * 1536 + HH + ca];
            wkb[k] = W[(2 + k) * 1536 + HH + cb];
        }
        const float bfa = bias[HH + ca], bfb = bias[HH + cb];
        for (int v = 0; v < VN; v++) {
            float aa = bfa, ab = bfb;
#pragma unroll
            for (int k = 0; k < DACT; k++) {
                const float e = emb[v * DACT + k];
                aa = fmaf(e, wka[k], aa);
                ab = fmaf(e, wkb[k], ab);
            }
            tblzf[v * 64 + tid].y = h2bits(__floats2half2_rn(0.5f * aa, 0.5f * ab));
        }
#pragma unroll
        for (int k = 0; k < DACT; k++) {
            wka[k] = W[(2 + k) * 1536 + 2 * HH + ca];
            wkb[k] = W[(2 + k) * 1536 + 2 * HH + cb];
        }
        const float boa = bias[2 * HH + ca], bob = bias[2 * HH + cb];
        for (int v = 0; v < VN; v++) {
            float aa = boa, ab = bob;
#pragma unroll
            for (int k = 0; k < DACT; k++) {
                const float e = emb[v * DACT + k];
                aa = fmaf(e, wka[k], aa);
                ab = fmaf(e, wkb[k], ab);
            }
            tblo[v * 64 + tid] = __floats2half2_rn(0.5f * aa, 0.5f * ab);
        }
    }
    const float mua = Mu[dir * HH + ca];
    const float mub = Mu[dir * HH + cb];
    __syncthreads();

    const int lane = tid & 31;
    const int wid  = tid >> 5;            // 0..1
    float* bufw = buf + wid * 160;        // 32 x 5 padded tile
    const int rstep = dir ? -(D2 / 2) : (D2 / 2);   // in half2 units

    const __half2 hhalf = __half2half2(__float2half_rn(0.5f));
    const __half2 hzero = __half2half2(__float2half_rn(0.0f));
    // tanh poly coefficients (fit on [-1.5,1.5]) and clamp bounds
    const __half2 pc1 = __half2half2(__float2half_rn(1.000282f));
    const __half2 pc3 = __half2half2(__float2half_rn(-0.324356f));
    const __half2 pc5 = __half2half2(__float2half_rn(0.100373f));
    const __half2 pc7 = __half2half2(__float2half_rn(-0.015381f));
    const __half2 clP = __half2half2(__float2half_rn(1.5f));
    const __half2 clN = __half2half2(__float2half_rn(-1.5f));
    __half2 c2 = hzero;

    __half2* hp = (__half2*)(g_h + ((size_t)b * TT + (dir ? TT - 1 : 0)) * D2
                             + (size_t)dir * HH + d0);
    float* wp_out = g_wp + ((size_t)b * 16 + unit * 2 + wid) * TT;

    for (int ch = 0; ch < TT / 4; ch++) {
#pragma unroll
        for (int j = 0; j < 4; j++) {
            const int i = ch * 4 + j;
            const int t = dir ? (TT - 1 - i) : i;
            const __half2 t0 = tsa[t];
            const __half2 t1 = tsb[t];
            const int off = ((int)vv[t]) + tid;
            const uint2 zfb = tblzf[off];
            const __half2 az = __hfma2(t0, wz0, __hfma2(t1, wz1, bits2h2(zfb.x)));
            const __half2 af = __hfma2(t0, wf0, __hfma2(t1, wf1, bits2h2(zfb.y)));
            const __half2 ao = __hfma2(t0, wo0, __hfma2(t1, wo1, tblo[off]));
            const __half2 z = qtanh_h2(az);
            const __half2 f = __hfma2(qtanh_h2(af), hhalf, hhalf);
            // o via fp16 polynomial (fma pipe, off the recurrence path)
            const __half2 xc = __hmax2(__hmin2(ao, clP), clN);
            const __half2 s2 = __hmul2(xc, xc);
            __half2 pp = __hfma2(s2, pc7, pc5);
            pp = __hfma2(s2, pp, pc3);
            pp = __hfma2(s2, pp, pc1);
            const __half2 w = __hmul2(pp, xc);           // ~tanh(ao')
            const __half2 o = __hfma2(w, hhalf, hhalf);  // sigmoid(ao)
            c2 = __hfma2(f, __hsub2(c2, z), z);          // f*c + (1-f)*z
            const __half2 hr = __hmax2(__hmul2(o, c2), hzero);
            *hp = hr; hp += rstep;
            const float2 hf2 = __half22float2(hr);
            bufw[lane * 5 + j] = fmaf(mua, hf2.x, mub * hf2.y);
        }
        __syncwarp();
        {
            const int tl = lane >> 3;                // t_local 0..3
            const int s  = lane & 7;
            float p = bufw[(s     ) * 5 + tl]
                    + bufw[(s +  8) * 5 + tl]
                    + bufw[(s + 16) * 5 + tl]
                    + bufw[(s + 24) * 5 + tl];
            p += __shfl_xor_sync(0xffffffffu, p, 4);
            p += __shfl_xor_sync(0xffffffffu, p, 2);
            p += __shfl_xor_sync(0xffffffffu, p, 1);
            if (s == 0) {
                const int i = ch * 4 + tl;
                wp_out[dir ? (TT - 1 - i) : i] = p;
            }
        }
        __syncwarp();
    }
}

// ---------------- K2: fused softmax + context + GEMV, one block per batch ----------------
#define ROWSTRIDE (64 * 17)   // 1088 floats per partial row

__global__ void __launch_bounds__(1024) finalize_kernel(
    const float* __restrict__ W_out,  // (64, 1024)
    const float* __restrict__ b_out,  // (64,)
    float* __restrict__ out)          // (B, 64)
{
    __shared__ float sm_acc[8 * ROWSTRIDE];  // 34816 B; phase1 reuses first 1024
    __shared__ float sm_attn[TT];
    __shared__ float sm_ctx[D2];
    __shared__ float red[32];

    const int b   = blockIdx.x;
    const int tid = threadIdx.x;
    const int lane = tid & 31, wid = tid >> 5;

    // ---- phase 1a: reduce 16 warp-partial rows -> logits ----
    {
        const int t  = tid & 511;
        const int hf = tid >> 9;                      // 0/1: rows [0,8) or [8,16)
        const float* wp = g_wp + ((size_t)b * 16 + hf * 8) * TT + t;
        float s = 0.0f;
#pragma unroll
        for (int r = 0; r < 8; r++) s += wp[(size_t)r * TT];
        sm_acc[hf * 512 + t] = s;
    }
    __syncthreads();
    float s_logit = -1e30f;
    if (tid < TT) s_logit = sm_acc[tid] + sm_acc[512 + tid];

    // ---- phase 1b: softmax over 512 ----
    float m = s_logit;
#pragma unroll
    for (int o = 16; o; o >>= 1) m = fmaxf(m, __shfl_xor_sync(0xffffffffu, m, o));
    if (lane == 0) red[wid] = m;
    __syncthreads();
    if (wid == 0) {
        float v = red[lane];
#pragma unroll
        for (int o = 16; o; o >>= 1) v = fmaxf(v, __shfl_xor_sync(0xffffffffu, v, o));
        if (lane == 0) red[0] = v;
    }
    __syncthreads();
    m = red[0];
    __syncthreads();

    float e = (tid < TT) ? fex2(1.4426950408889634f * (s_logit - m)) : 0.0f;
    float su = e;
#pragma unroll
    for (int o = 16; o; o >>= 1) su += __shfl_xor_sync(0xffffffffu, su, o);
    if (lane == 0) red[wid] = su;
    __syncthreads();
    if (wid == 0) {
        float v = red[lane];
#pragma unroll
        for (int o = 16; o; o >>= 1) v += __shfl_xor_sync(0xffffffffu, v, o);
        if (lane == 0) red[0] = v;
    }
    __syncthreads();
    if (tid < TT) sm_attn[tid] = e / red[0];
    __syncthreads();

    // ---- phase 2: context with 32B evict_first loads ----
    {
        const int tg  = tid >> 6;                     // t-group 0..15
        const int dcw = tid & 63;                     // d-chunk index (16 d each)
        const __half* hb = g_h + (size_t)b * TT * D2 + dcw * 16;

        float acc[16];
#pragma unroll
        for (int j = 0; j < 16; j++) acc[j] = 0.0f;

        ulonglong4 cur[2], nxt[2];
        float ac[2], an[2];
#pragma unroll
        for (int i = 0; i < 2; i++) {
            const int t = tg + i * 16;
            cur[i] = ldg_ef_u8(hb + (size_t)t * D2);
            ac[i] = sm_attn[t];
        }
        for (int g = 0; g < 16; g++) {
            const int gn = (g + 1) & 15;             // wraps on last (harmless reload)
#pragma unroll
            for (int i = 0; i < 2; i++) {
                const int t = tg + (gn * 2 + i) * 16;
                nxt[i] = ldg_ef_u8(hb + (size_t)t * D2);
                an[i] = sm_attn[t];
            }
#pragma unroll
            for (int i = 0; i < 2; i++) {
                const float a = ac[i];
#define ACC_U64(W64, BASE)                                             \
                {                                                      \
                    float2 qa = __half22float2(bits2h2((unsigned)(W64)));          \
                    float2 qb = __half22float2(bits2h2((unsigned)((W64) >> 32)));  \
                    acc[(BASE) + 0] = fmaf(a, qa.x, acc[(BASE) + 0]);  \
                    acc[(BASE) + 1] = fmaf(a, qa.y, acc[(BASE) + 1]);  \
                    acc[(BASE) + 2] = fmaf(a, qb.x, acc[(BASE) + 2]);  \
                    acc[(BASE) + 3] = fmaf(a, qb.y, acc[(BASE) + 3]);  \
                }
                ACC_U64(cur[i].x, 0);
                ACC_U64(cur[i].y, 4);
                ACC_U64(cur[i].z, 8);
                ACC_U64(cur[i].w, 12);
#undef ACC_U64
            }
#pragma unroll
            for (int i = 0; i < 2; i++) { cur[i] = nxt[i]; ac[i] = an[i]; }
        }

        // two-stage 16 -> 8 partial rows in padded smem
        float* sp = sm_acc + (tg & 7) * ROWSTRIDE + dcw * 17;
        if (tg < 8) {
#pragma unroll
            for (int j = 0; j < 16; j++) sp[j] = acc[j];
        }
        __syncthreads();
        if (tg >= 8) {
#pragma unroll
            for (int j = 0; j < 16; j++) sp[j] += acc[j];
        }
    }
    __syncthreads();

    // reduce 8 partial rows per d, relu -> ctx
    {
        const int chunk = tid >> 4, jj = tid & 15;
        const float* base = sm_acc + chunk * 17 + jj;
        float v0 = base[0 * ROWSTRIDE] + base[1 * ROWSTRIDE];
        float v1 = base[2 * ROWSTRIDE] + base[3 * ROWSTRIDE];
        float v2 = base[4 * ROWSTRIDE] + base[5 * ROWSTRIDE];
        float v3 = base[6 * ROWSTRIDE] + base[7 * ROWSTRIDE];
        sm_ctx[tid] = fmaxf((v0 + v1) + (v2 + v3), 0.0f);
    }
    __syncthreads();

    // ---- phase 3: GEMV 64 x 1024 (32 warps x 2 rows) ----
#pragma unroll
    for (int r = 0; r < 2; r++) {
        const int o = wid * 2 + r;
        const float* wrow = W_out + (size_t)o * D2;
        float v = 0.0f;
#pragma unroll
        for (int k = 0; k < D2 / 32; k++)
            v = fmaf(sm_ctx[lane + k * 32], wrow[lane + k * 32], v);
#pragma unroll
        for (int off = 16; off; off >>= 1) v += __shfl_xor_sync(0xffffffffu, v, off);
        if (lane == 0) out[(size_t)b * NOUT + o] = v + b_out[o];
    }
}

extern "C" void kernel_launch(void* const* d_in, const int* in_sizes, int n_in,
                              void* d_out, int out_size) {
    const float* x     = (const float*)d_in[0];
    const float* emb   = (const float*)d_in[1];
    const float* Wf    = (const float*)d_in[2];
    const float* bf    = (const float*)d_in[3];
    const float* Wb    = (const float*)d_in[4];
    const float* bb    = (const float*)d_in[5];
    const float* Mu    = (const float*)d_in[6];
    const float* W_out = (const float*)d_in[7];
    const float* b_out = (const float*)d_in[8];
    float* out = (float*)d_out;

    // scan smem: 8192 + 4096 + 2048 + 2048 + 1024 + 1280 = 18688 B (< 48KB default)
    scan_kernel<<<dim3(BB, 8), 64, 18688>>>(x, emb, Wf, bf, Wb, bb, Mu);
    finalize_kernel<<<BB, 1024>>>(W_out, b_out, out);
}

// round 17
// speedup vs baseline: 1.7640x; 1.1415x over previous
#include <cuda_runtime.h>
#include <cuda_fp16.h>
#include <cstdint>

#define BB 128
#define TT 512
#define HH 512
#define D2 1024
#define NOUT 64
#define VN 16
#define DACT 10

// device scratch (no allocations allowed)
__device__ __half g_h[(size_t)BB * TT * D2];   // 134 MB relu(out) [b][t][d], fp16
__device__ float g_wp[(size_t)BB * 16 * TT];   // warp logit partials [b][row][t]

__device__ __forceinline__ float fex2(float x) {
    float y; asm("ex2.approx.f32 %0, %1;" : "=f"(y) : "f"(x)); return y;
}
__device__ __forceinline__ __half2 qtanh_h2(__half2 x) {
    unsigned xi = *reinterpret_cast<unsigned*>(&x);
    unsigned yi;
    asm("tanh.approx.f16x2 %0, %1;" : "=r"(yi) : "r"(xi));
    return *reinterpret_cast<__half2*>(&yi);
}
__device__ __forceinline__ unsigned h2bits(__half2 v) {
    return *reinterpret_cast<unsigned*>(&v);
}
__device__ __forceinline__ __half2 bits2h2(unsigned v) {
    return *reinterpret_cast<__half2*>(&v);
}
// 256-bit evict-first load (sm_103a requires .v4.b64 width for the L2 hint)
__device__ __forceinline__ ulonglong4 ldg_ef_u8(const void* p) {
    ulonglong4 v;
    asm volatile("ld.global.L2::evict_first.v4.b64 {%0,%1,%2,%3}, [%4];"
                 : "=l"(v.x), "=l"(v.y), "=l"(v.z), "=l"(v.w) : "l"(p));
    return v;
}

// ---------------- K1: batch-gate + scan (break the per-iter latency chain) ----------------
// Per chunk of 8 timesteps: phase A computes z/f/o for all 8 (fully independent, deep ILP);
// phase B runs the 8-step recurrence (short serial chain). o-gate via fp16 polynomial.
// grid (B, 8); unit = dir*4 + q; 64 threads; thread owns channel pair d0 = q*128+tid*2.
// smem (20736 B): tblzf uint2[VN*64] | tblo half2[VN*64] | tsa half2[TT] | tsb half2[TT]
//                 | vv short[TT] | buf float[2*288]
extern __shared__ float s_raw[];

__global__ void __launch_bounds__(64, 7) scan_kernel(
    const float* __restrict__ x,   // (B,T,3)
    const float* __restrict__ emb, // (16,10)
    const float* __restrict__ Wf, const float* __restrict__ bfw,
    const float* __restrict__ Wb, const float* __restrict__ bbw,
    const float* __restrict__ Mu)  // (2H,1)
{
    const int b    = blockIdx.x;
    const int unit = blockIdx.y;          // 0..7
    const int dir  = unit >> 2;
    const int q    = unit & 3;
    const int tid  = threadIdx.x;         // 0..63
    const int d0   = q * 128 + tid * 2;   // channel pair within dir

    uint2*   tblzf = (uint2*)s_raw;                    // VN*64 uint2  (8192 B)
    __half2* tblo  = (__half2*)(tblzf + VN * 64);      // VN*64 half2  (4096 B)
    __half2* tsa   = tblo + VN * 64;                   // TT half2     (2048 B)
    __half2* tsb   = tsa + TT;                         // TT half2     (2048 B)
    short*   vv    = (short*)(tsb + TT);               // TT           (1024 B)
    float*   buf   = (float*)(vv + TT);                // 2*288        (2304 B)

    const float* W    = dir ? Wb : Wf;
    const float* bias = dir ? bbw : bfw;

    // stage x row into smem (splatted half2)
    for (int t = tid; t < TT; t += 64) {
        const float* xp = x + ((size_t)b * TT + t) * 3;
        tsa[t] = __half2half2(__float2half_rn(xp[0]));
        tsb[t] = __half2half2(__float2half_rn(xp[1]));
        vv[t]  = (short)(((int)xp[2]) << 6);           // v*64
    }

    const int ca = d0, cb = d0 + 1;
    // ts-part weights per gate, channel pair. f/o gates prescaled by 0.5 (sigmoid trick).
    const __half2 wz0 = __floats2half2_rn(W[ca], W[cb]);
    const __half2 wz1 = __floats2half2_rn(W[1536 + ca], W[1536 + cb]);
    const __half2 wf0 = __floats2half2_rn(0.5f * W[HH + ca], 0.5f * W[HH + cb]);
    const __half2 wf1 = __floats2half2_rn(0.5f * W[1536 + HH + ca], 0.5f * W[1536 + HH + cb]);
    const __half2 wo0 = __floats2half2_rn(0.5f * W[2 * HH + ca], 0.5f * W[2 * HH + cb]);
    const __half2 wo1 = __floats2half2_rn(0.5f * W[1536 + 2 * HH + ca], 0.5f * W[1536 + 2 * HH + cb]);

    // build tables (f32 accumulate, store half2). z: full; f,o: prescaled 0.5.
    {
        float wka[DACT], wkb[DACT];
#pragma unroll
        for (int k = 0; k < DACT; k++) {
            wka[k] = W[(2 + k) * 1536 + ca];
            wkb[k] = W[(2 + k) * 1536 + cb];
        }
        const float bza = bias[ca], bzb = bias[cb];
        for (int v = 0; v < VN; v++) {
            float aa = bza, ab = bzb;
#pragma unroll
            for (int k = 0; k < DACT; k++) {
                const float e = emb[v * DACT + k];
                aa = fmaf(e, wka[k], aa);
                ab = fmaf(e, wkb[k], ab);
            }
            tblzf[v * 64 + tid].x = h2bits(__floats2half2_rn(aa, ab));
        }
#pragma unroll
        for (int k = 0; k < DACT; k++) {
            wka[k] = W[(2 + k) * 1536 + HH + ca];
            wkb[k] = W[(2 + k) * 1536 + HH + cb];
        }
        const float bfa = bias[HH + ca], bfb = bias[HH + cb];
        for (int v = 0; v < VN; v++) {
            float aa = bfa, ab = bfb;
#pragma unroll
            for (int k = 0; k < DACT; k++) {
                const float e = emb[v * DACT + k];
                aa = fmaf(e, wka[k], aa);
                ab = fmaf(e, wkb[k], ab);
            }
            tblzf[v * 64 + tid].y = h2bits(__floats2half2_rn(0.5f * aa, 0.5f * ab));
        }
#pragma unroll
        for (int k = 0; k < DACT; k++) {
            wka[k] = W[(2 + k) * 1536 + 2 * HH + ca];
            wkb[k] = W[(2 + k) * 1536 + 2 * HH + cb];
        }
        const float boa = bias[2 * HH + ca], bob = bias[2 * HH + cb];
        for (int v = 0; v < VN; v++) {
            float aa = boa, ab = bob;
#pragma unroll
            for (int k = 0; k < DACT; k++) {
                const float e = emb[v * DACT + k];
                aa = fmaf(e, wka[k], aa);
                ab = fmaf(e, wkb[k], ab);
            }
            tblo[v * 64 + tid] = __floats2half2_rn(0.5f * aa, 0.5f * ab);
        }
    }
    const float mua = Mu[dir * HH + ca];
    const float mub = Mu[dir * HH + cb];
    __syncthreads();

    const int lane = tid & 31;
    const int wid  = tid >> 5;            // 0..1
    float* bufw = buf + wid * 288;        // 32 x 9 padded tile
    const int rstep = dir ? -(D2 / 2) : (D2 / 2);   // in half2 units

    const __half2 hhalf = __half2half2(__float2half_rn(0.5f));
    const __half2 hzero = __half2half2(__float2half_rn(0.0f));
    // tanh poly coefficients (fit on [-1.5,1.5]) and clamp bounds
    const __half2 pc1 = __half2half2(__float2half_rn(1.000282f));
    const __half2 pc3 = __half2half2(__float2half_rn(-0.324356f));
    const __half2 pc5 = __half2half2(__float2half_rn(0.100373f));
    const __half2 pc7 = __half2half2(__float2half_rn(-0.015381f));
    const __half2 clP = __half2half2(__float2half_rn(1.5f));
    const __half2 clN = __half2half2(__float2half_rn(-1.5f));
    __half2 c2 = hzero;

    __half2* hp = (__half2*)(g_h + ((size_t)b * TT + (dir ? TT - 1 : 0)) * D2
                             + (size_t)dir * HH + d0);
    float* wp_out = g_wp + ((size_t)b * 16 + unit * 2 + wid) * TT;

    for (int ch = 0; ch < TT / 8; ch++) {
        __half2 zv[8], fv[8], ov[8];
        // ---- phase A: gates for 8 timesteps (fully independent, deep ILP) ----
#pragma unroll
        for (int j = 0; j < 8; j++) {
            const int i = ch * 8 + j;
            const int t = dir ? (TT - 1 - i) : i;
            const __half2 t0 = tsa[t];
            const __half2 t1 = tsb[t];
            const int off = ((int)vv[t]) + tid;
            const uint2 zfb = tblzf[off];
            const __half2 az = __hfma2(t0, wz0, __hfma2(t1, wz1, bits2h2(zfb.x)));
            const __half2 af = __hfma2(t0, wf0, __hfma2(t1, wf1, bits2h2(zfb.y)));
            const __half2 ao = __hfma2(t0, wo0, __hfma2(t1, wo1, tblo[off]));
            zv[j] = qtanh_h2(az);
            fv[j] = __hfma2(qtanh_h2(af), hhalf, hhalf);
            // o via fp16 polynomial (fma pipe)
            const __half2 xc = __hmax2(__hmin2(ao, clP), clN);
            const __half2 s2 = __hmul2(xc, xc);
            __half2 pp = __hfma2(s2, pc7, pc5);
            pp = __hfma2(s2, pp, pc3);
            pp = __hfma2(s2, pp, pc1);
            ov[j] = __hfma2(__hmul2(pp, xc), hhalf, hhalf);
        }
        // ---- phase B: 8-step recurrence (short serial chain) ----
#pragma unroll
        for (int j = 0; j < 8; j++) {
            c2 = __hfma2(fv[j], __hsub2(c2, zv[j]), zv[j]);   // f*c + (1-f)*z
            const __half2 hr = __hmax2(__hmul2(ov[j], c2), hzero);
            *hp = hr; hp += rstep;
            const float2 hf2 = __half22float2(hr);
            bufw[lane * 9 + j] = fmaf(mua, hf2.x, mub * hf2.y);
        }
        __syncwarp();
        // ---- logit transpose-reduce: 8 t_local, 4 lanes each ----
        {
            const int tl = lane >> 2;                // t_local 0..7
            const int s  = lane & 3;
            float p = 0.0f;
#pragma unroll
            for (int k = 0; k < 8; k++) p += bufw[(s + 4 * k) * 9 + tl];
            p += __shfl_xor_sync(0xffffffffu, p, 2);
            p += __shfl_xor_sync(0xffffffffu, p, 1);
            if (s == 0) {
                const int i = ch * 8 + tl;
                wp_out[dir ? (TT - 1 - i) : i] = p;
            }
        }
        __syncwarp();
    }
}

// ---------------- K2: fused softmax + context + GEMV, one block per batch ----------------
#define ROWSTRIDE (64 * 17)   // 1088 floats per partial row

__global__ void __launch_bounds__(1024) finalize_kernel(
    const float* __restrict__ W_out,  // (64, 1024)
    const float* __restrict__ b_out,  // (64,)
    float* __restrict__ out)          // (B, 64)
{
    __shared__ float sm_acc[8 * ROWSTRIDE];  // 34816 B; phase1 reuses first 1024
    __shared__ float sm_attn[TT];
    __shared__ float sm_ctx[D2];
    __shared__ float red[32];

    const int b   = blockIdx.x;
    const int tid = threadIdx.x;
    const int lane = tid & 31, wid = tid >> 5;

    // ---- phase 1a: reduce 16 warp-partial rows -> logits ----
    {
        const int t  = tid & 511;
        const int hf = tid >> 9;                      // 0/1: rows [0,8) or [8,16)
        const float* wp = g_wp + ((size_t)b * 16 + hf * 8) * TT + t;
        float s = 0.0f;
#pragma unroll
        for (int r = 0; r < 8; r++) s += wp[(size_t)r * TT];
        sm_acc[hf * 512 + t] = s;
    }
    __syncthreads();
    float s_logit = -1e30f;
    if (tid < TT) s_logit = sm_acc[tid] + sm_acc[512 + tid];

    // ---- phase 1b: softmax over 512 ----
    float m = s_logit;
#pragma unroll
    for (int o = 16; o; o >>= 1) m = fmaxf(m, __shfl_xor_sync(0xffffffffu, m, o));
    if (lane == 0) red[wid] = m;
    __syncthreads();
    if (wid == 0) {
        float v = red[lane];
#pragma unroll
        for (int o = 16; o; o >>= 1) v = fmaxf(v, __shfl_xor_sync(0xffffffffu, v, o));
        if (lane == 0) red[0] = v;
    }
    __syncthreads();
    m = red[0];
    __syncthreads();

    float e = (tid < TT) ? fex2(1.4426950408889634f * (s_logit - m)) : 0.0f;
    float su = e;
#pragma unroll
    for (int o = 16; o; o >>= 1) su += __shfl_xor_sync(0xffffffffu, su, o);
    if (lane == 0) red[wid] = su;
    __syncthreads();
    if (wid == 0) {
        float v = red[lane];
#pragma unroll
        for (int o = 16; o; o >>= 1) v += __shfl_xor_sync(0xffffffffu, v, o);
        if (lane == 0) red[0] = v;
    }
    __syncthreads();
    if (tid < TT) sm_attn[tid] = e / red[0];
    __syncthreads();

    // ---- phase 2: context with 32B evict_first loads ----
    {
        const int tg  = tid >> 6;                     // t-group 0..15
        const int dcw = tid & 63;                     // d-chunk index (16 d each)
        const __half* hb = g_h + (size_t)b * TT * D2 + dcw * 16;

        float acc[16];
#pragma unroll
        for (int j = 0; j < 16; j++) acc[j] = 0.0f;

        ulonglong4 cur[2], nxt[2];
        float ac[2], an[2];
#pragma unroll
        for (int i = 0; i < 2; i++) {
            const int t = tg + i * 16;
            cur[i] = ldg_ef_u8(hb + (size_t)t * D2);
            ac[i] = sm_attn[t];
        }
        for (int g = 0; g < 16; g++) {
            const int gn = (g + 1) & 15;             // wraps on last (harmless reload)
#pragma unroll
            for (int i = 0; i < 2; i++) {
                const int t = tg + (gn * 2 + i) * 16;
                nxt[i] = ldg_ef_u8(hb + (size_t)t * D2);
                an[i] = sm_attn[t];
            }
#pragma unroll
            for (int i = 0; i < 2; i++) {
                const float a = ac[i];
#define ACC_U64(W64, BASE)                                             \
                {                                                      \
                    float2 qa = __half22float2(bits2h2((unsigned)(W64)));          \
                    float2 qb = __half22float2(bits2h2((unsigned)((W64) >> 32)));  \
                    acc[(BASE) + 0] = fmaf(a, qa.x, acc[(BASE) + 0]);  \
                    acc[(BASE) + 1] = fmaf(a, qa.y, acc[(BASE) + 1]);  \
                    acc[(BASE) + 2] = fmaf(a, qb.x, acc[(BASE) + 2]);  \
                    acc[(BASE) + 3] = fmaf(a, qb.y, acc[(BASE) + 3]);  \
                }
                ACC_U64(cur[i].x, 0);
                ACC_U64(cur[i].y, 4);
                ACC_U64(cur[i].z, 8);
                ACC_U64(cur[i].w, 12);
#undef ACC_U64
            }
#pragma unroll
            for (int i = 0; i < 2; i++) { cur[i] = nxt[i]; ac[i] = an[i]; }
        }

        // two-stage 16 -> 8 partial rows in padded smem
        float* sp = sm_acc + (tg & 7) * ROWSTRIDE + dcw * 17;
        if (tg < 8) {
#pragma unroll
            for (int j = 0; j < 16; j++) sp[j] = acc[j];
        }
        __syncthreads();
        if (tg >= 8) {
#pragma unroll
            for (int j = 0; j < 16; j++) sp[j] += acc[j];
        }
    }
    __syncthreads();

    // reduce 8 partial rows per d, relu -> ctx
    {
        const int chunk = tid >> 4, jj = tid & 15;
        const float* base = sm_acc + chunk * 17 + jj;
        float v0 = base[0 * ROWSTRIDE] + base[1 * ROWSTRIDE];
        float v1 = base[2 * ROWSTRIDE] + base[3 * ROWSTRIDE];
        float v2 = base[4 * ROWSTRIDE] + base[5 * ROWSTRIDE];
        float v3 = base[6 * ROWSTRIDE] + base[7 * ROWSTRIDE];
        sm_ctx[tid] = fmaxf((v0 + v1) + (v2 + v3), 0.0f);
    }
    __syncthreads();

    // ---- phase 3: GEMV 64 x 1024 (32 warps x 2 rows) ----
#pragma unroll
    for (int r = 0; r < 2; r++) {
        const int o = wid * 2 + r;
        const float* wrow = W_out + (size_t)o * D2;
        float v = 0.0f;
#pragma unroll
        for (int k = 0; k < D2 / 32; k++)
            v = fmaf(sm_ctx[lane + k * 32], wrow[lane + k * 32], v);
#pragma unroll
        for (int off = 16; off; off >>= 1) v += __shfl_xor_sync(0xffffffffu, v, off);
        if (lane == 0) out[(size_t)b * NOUT + o] = v + b_out[o];
    }
}

extern "C" void kernel_launch(void* const* d_in, const int* in_sizes, int n_in,
                              void* d_out, int out_size) {
    const float* x     = (const float*)d_in[0];
    const float* emb   = (const float*)d_in[1];
    const float* Wf    = (const float*)d_in[2];
    const float* bf    = (const float*)d_in[3];
    const float* Wb    = (const float*)d_in[4];
    const float* bb    = (const float*)d_in[5];
    const float* Mu    = (const float*)d_in[6];
    const float* W_out = (const float*)d_in[7];
    const float* b_out = (const float*)d_in[8];
    float* out = (float*)d_out;

    // scan smem: 8192 + 4096 + 2048 + 2048 + 1024 + 2304 = 19712 B (< 48KB default)
    scan_kernel<<<dim3(BB, 8), 64, 19712>>>(x, emb, Wf, bf, Wb, bb, Mu);
    finalize_kernel<<<BB, 1024>>>(W_out, b_out, out);
}